// round 2
// baseline (speedup 1.0000x reference)
#include <cuda_runtime.h>

// Global accumulators (device globals — no allocation allowed).
__device__ double g_loss;
__device__ double g_denom;

__global__ void zero_accum_kernel() {
    g_loss = 0.0;
    g_denom = 0.0;
}

#define TW 32
#define TH 16
#define HALO_W (TW + 2)
#define HALO_H (TH + 2)
#define NTHREADS (TW * TH)

__global__ __launch_bounds__(NTHREADS) void normal_loss_kernel(
    const float* __restrict__ pred,
    const float* __restrict__ gt,
    const float* __restrict__ mask,
    int B, int H, int W)
{
    __shared__ float sp[3][HALO_H][HALO_W];
    __shared__ float sg[3][HALO_H][HALO_W];
    __shared__ float red_l[NTHREADS / 32];
    __shared__ float red_m[NTHREADS / 32];

    const int b  = blockIdx.z;
    const int x0 = blockIdx.x * TW;
    const int y0 = blockIdx.y * TH;
    const int tx = threadIdx.x;
    const int ty = threadIdx.y;
    const int tid = ty * TW + tx;

    const long long plane = (long long)H * W;
    const float* pb = pred + (long long)b * 3 * plane;
    const float* gb = gt   + (long long)b * 3 * plane;
    const float* mb = mask + (long long)b * plane;

    // ---- Load halo tiles (zero padding outside the image) ----
    const int TOT = HALO_H * HALO_W;   // 612
    for (int idx = tid; idx < TOT; idx += NTHREADS) {
        int r  = idx / HALO_W;
        int cc = idx - r * HALO_W;
        int gy = y0 + r - 1;
        int gx = x0 + cc - 1;
        bool inb = (gy >= 0) && (gy < H) && (gx >= 0) && (gx < W);
        long long off = (long long)gy * W + gx;
        #pragma unroll
        for (int c = 0; c < 3; c++) {
            sp[c][r][cc] = inb ? __ldg(pb + c * plane + off) : 0.0f;
            sg[c][r][cc] = inb ? __ldg(gb + c * plane + off) : 0.0f;
        }
    }
    __syncthreads();

    // ---- Compute per-pixel loss contribution ----
    float lsum = 0.0f;
    float msum = 0.0f;

    const int px = x0 + tx;
    const int py = y0 + ty;
    if (px < W && py < H) {
        const int r = ty + 1;
        const int c = tx + 1;

        float ax[3], ay[3];   // pred gradients per channel
        float bx[3], by[3];   // gt gradients per channel
        #pragma unroll
        for (int ch = 0; ch < 3; ch++) {
            // gx = 3 * sum_rows (right - left)
            float pgx = (sp[ch][r-1][c+1] + sp[ch][r][c+1] + sp[ch][r+1][c+1])
                      - (sp[ch][r-1][c-1] + sp[ch][r][c-1] + sp[ch][r+1][c-1]);
            // gy = 3 * (bottom row sum - top row sum)
            float pgy = (sp[ch][r+1][c-1] + sp[ch][r+1][c] + sp[ch][r+1][c+1])
                      - (sp[ch][r-1][c-1] + sp[ch][r-1][c] + sp[ch][r-1][c+1]);
            ax[ch] = 3.0f * pgx;
            ay[ch] = 3.0f * pgy;

            float ggx = (sg[ch][r-1][c+1] + sg[ch][r][c+1] + sg[ch][r+1][c+1])
                      - (sg[ch][r-1][c-1] + sg[ch][r][c-1] + sg[ch][r+1][c-1]);
            float ggy = (sg[ch][r+1][c-1] + sg[ch][r+1][c] + sg[ch][r+1][c+1])
                      - (sg[ch][r-1][c-1] + sg[ch][r-1][c] + sg[ch][r-1][c+1]);
            bx[ch] = 3.0f * ggx;
            by[ch] = 3.0f * ggy;
        }

        // normal = grad_x_vec x grad_y_vec (cross product), then normalize
        float pnx = ax[1] * ay[2] - ax[2] * ay[1];
        float pny = ax[2] * ay[0] - ax[0] * ay[2];
        float pnz = ax[0] * ay[1] - ax[1] * ay[0];
        float pn = sqrtf(pnx * pnx + pny * pny + pnz * pnz) + 1e-10f;
        float pinv = 1.0f / pn;
        pnx *= pinv; pny *= pinv; pnz *= pinv;

        float gnx = bx[1] * by[2] - bx[2] * by[1];
        float gny = bx[2] * by[0] - bx[0] * by[2];
        float gnz = bx[0] * by[1] - bx[1] * by[0];
        float gn = sqrtf(gnx * gnx + gny * gny + gnz * gnz) + 1e-10f;
        float ginv = 1.0f / gn;
        gnx *= ginv; gny *= ginv; gnz *= ginv;

        float mval = __ldg(mb + (long long)py * W + px);
        lsum = mval * (fabsf(pnx - gnx) + fabsf(pny - gny) + fabsf(pnz - gnz));
        msum = mval;
    }

    // ---- Block reduction ----
    #pragma unroll
    for (int o = 16; o > 0; o >>= 1) {
        lsum += __shfl_down_sync(0xFFFFFFFFu, lsum, o);
        msum += __shfl_down_sync(0xFFFFFFFFu, msum, o);
    }
    const int warp = tid >> 5;
    const int lane = tid & 31;
    if (lane == 0) {
        red_l[warp] = lsum;
        red_m[warp] = msum;
    }
    __syncthreads();
    if (tid == 0) {
        float tl = 0.0f, tm = 0.0f;
        #pragma unroll
        for (int w = 0; w < NTHREADS / 32; w++) {
            tl += red_l[w];
            tm += red_m[w];
        }
        atomicAdd(&g_loss, (double)tl);
        atomicAdd(&g_denom, (double)tm);
    }
}

__global__ void finalize_kernel(float* __restrict__ out) {
    out[0] = (float)(g_loss / g_denom);
}

extern "C" void kernel_launch(void* const* d_in, const int* in_sizes, int n_in,
                              void* d_out, int out_size)
{
    const float* pred = (const float*)d_in[0];
    const float* gt   = (const float*)d_in[1];
    const float* mask = (const float*)d_in[2];
    float* out = (float*)d_out;

    const int H = 384;
    const int W = 1280;
    const int B = in_sizes[2] / (H * W);   // mask elements = B*H*W

    zero_accum_kernel<<<1, 1>>>();

    dim3 block(TW, TH);
    dim3 grid((W + TW - 1) / TW, (H + TH - 1) / TH, B);
    normal_loss_kernel<<<grid, block>>>(pred, gt, mask, B, H, W);

    finalize_kernel<<<1, 1>>>(out);
}